// round 12
// baseline (speedup 1.0000x reference)
#include <cuda_runtime.h>

// Transitive closure of {0} under (left,right) == reference's 8192-step fixed
// point. One-CTA BFS-until-converged, atomic-free. R11 showed the loop is
// LATENCY-bound per round (volatile-LDS chain + barrier), and extra sweeps
// don't cut round count. This round:
//   - SWEEPS=1: round = one LDS.64 + compare + BAR (no serial sweep chain)
//   - TWO-LEVEL expansion: children staged in smem as int16; expanding node j
//     sets children AND grandchildren -> rounds ~= depth/2 + 1.
//     Stores are idempotent (constant 1) so duplicate expansion is harmless.
//   - byte-per-node smem map; owner-side change detection; __syncthreads_or.

#define NNODES    8192
#define NTHREADS  1024
#define DONE_ALL  0x0101010101010101ull

__global__ __launch_bounds__(NTHREADS, 1)
void DAGGenome_reach_kernel(const int* __restrict__ left,
                            const int* __restrict__ right,
                            float* __restrict__ out)
{
    __shared__ __align__(16) unsigned char reach8[NNODES];
    __shared__ __align__(16) short sl[NNODES];   // left children, int16
    __shared__ __align__(16) short sr[NNODES];   // right children, int16

    const int tid = threadIdx.x;

    // --- prologue: children from gmem (coalesced int4), keep in regs,
    //     and stage as int16 in smem for grandchild lookups ---
    const int4* lp = (const int4*)left  + tid * 2;
    const int4* rp = (const int4*)right + tid * 2;
    const int4 l0 = lp[0], l1 = lp[1];
    const int4 r0 = rp[0], r1 = rp[1];
    const int cl[8] = { l0.x, l0.y, l0.z, l0.w, l1.x, l1.y, l1.z, l1.w };
    const int cr[8] = { r0.x, r0.y, r0.z, r0.w, r1.x, r1.y, r1.z, r1.w };

    uint4 pl, pr;
    pl.x = (l0.x & 0xffff) | (l0.y << 16);
    pl.y = (l0.z & 0xffff) | (l0.w << 16);
    pl.z = (l1.x & 0xffff) | (l1.y << 16);
    pl.w = (l1.z & 0xffff) | (l1.w << 16);
    pr.x = (r0.x & 0xffff) | (r0.y << 16);
    pr.y = (r0.z & 0xffff) | (r0.w << 16);
    pr.z = (r1.x & 0xffff) | (r1.y << 16);
    pr.w = (r1.z & 0xffff) | (r1.w << 16);
    ((uint4*)sl)[tid] = pl;
    ((uint4*)sr)[tid] = pr;

    ((unsigned long long*)reach8)[tid] = 0ull;   // zero byte map
    if (tid == 0) reach8[0] = 1;                 // seed node 0 (same thread: ordered)

    volatile unsigned long long* vmy =
        (volatile unsigned long long*)reach8 + tid;   // my 8 bytes
    volatile unsigned char* vr = (volatile unsigned char*)reach8;

    unsigned long long done64 = 0;   // 0x01 byte per already-expanded node
    __syncthreads();

    // --- BFS, 2 levels per round, one BAR.RED per round ---
    for (;;) {
        int lc_flag = 0;

        if (done64 != DONE_ALL) {
            const unsigned long long pending = (*vmy) & ~done64;
            if (pending) {
                lc_flag = 1;
                done64 |= pending;
                #pragma unroll
                for (int j = 0; j < 8; j++) {
                    if (pending & (1ull << (8 * j))) {
                        const int a = cl[j];
                        if (a >= 0) {
                            vr[a] = 1;
                            const int ga = sl[a], gb = sr[a];
                            if (ga >= 0) vr[ga] = 1;
                            if (gb >= 0) vr[gb] = 1;
                        }
                        const int b = cr[j];
                        if (b >= 0) {
                            vr[b] = 1;
                            const int ha = sl[b], hb = sr[b];
                            if (ha >= 0) vr[ha] = 1;
                            if (hb >= 0) vr[hb] = 1;
                        }
                    }
                }
            }
        }

        if (!__syncthreads_or(lc_flag)) break;
    }

    // --- float32 output: my 8 bytes -> 2x float4 stores ---
    const unsigned long long v = *vmy;
    float4 o0, o1;
    o0.x = (v & 0x01ull)      ? 1.0f : 0.0f;
    o0.y = (v & (1ull << 8))  ? 1.0f : 0.0f;
    o0.z = (v & (1ull << 16)) ? 1.0f : 0.0f;
    o0.w = (v & (1ull << 24)) ? 1.0f : 0.0f;
    o1.x = (v & (1ull << 32)) ? 1.0f : 0.0f;
    o1.y = (v & (1ull << 40)) ? 1.0f : 0.0f;
    o1.z = (v & (1ull << 48)) ? 1.0f : 0.0f;
    o1.w = (v & (1ull << 56)) ? 1.0f : 0.0f;
    float4* op = (float4*)out + tid * 2;
    op[0] = o0;
    op[1] = o1;
}

extern "C" void kernel_launch(void* const* d_in, const int* in_sizes, int n_in,
                              void* d_out, int out_size)
{
    const int* left  = (const int*)d_in[1];
    const int* right = (const int*)d_in[2];
    float* out = (float*)d_out;

    DAGGenome_reach_kernel<<<1, NTHREADS>>>(left, right, out);
}